// round 15
// baseline (speedup 1.0000x reference)
#include <cuda_runtime.h>
#include <cuda_fp16.h>
#include <math.h>

#define ATTN_OFF 262144          // B*1024 head elems, then attn [B,T,T]
#define GBLK 256                 // 256 blocks x 256 threads, 2 per SM

// ------------------- device globals (no allocation allowed) -------------------
__device__ __half g_UHh [33554432];        // [B*T, M] fp16 (67 MB)
__device__ __half g_Hh  [33554432];        // fp16 copy of H (67 MB)
__device__ __half g_WdTh[512 * 1024];      // W_d fp16, native [n=512][k=1024] (mma B layout)
__device__ float  g_UdT [512 * 512];       // U_d^T fp32 [m][n]
__device__ __half g_Wh  [2048 * 1024];     // fused W fp16, rows = permuted n' = p*4+gate
__device__ float  g_bias[2048];            // (b_ih+b_hh) permuted [p*4+gate]
__device__ __half g_qhA [256 * 1024];      // state [d(512); s(512)] fp16, ping
__device__ __half g_qhB [256 * 1024];      // state pong
__device__ __half g_qct [256 * 512];       // ct fp16
__device__ float  g_s   [131072];          // cell state fp32
__device__ float  g_dout[131072];          // d fp32 (for out head)
__device__ float  g_ct  [131072];          // ct fp32 (for out head)
__device__ float  g_wqp [4 * 131072];      // 4 k-quarter partials of wq

__device__ unsigned g_bar_count = 0;
__device__ unsigned g_bar_gen   = 0;

// ------------------- helpers -------------------
__device__ __forceinline__ float tanh_fast(float x) {
    float y;
    asm("tanh.approx.f32 %0, %1;" : "=f"(y) : "f"(x));
    return y;
}
__device__ __forceinline__ float sigmoid_fast(float x) {
    return 1.f / (1.f + __expf(-x));
}
__device__ __forceinline__ unsigned long long pack2(float x) {
    unsigned long long r;
    asm("mov.b64 %0, {%1, %1};" : "=l"(r) : "f"(x));
    return r;
}
__device__ __forceinline__ void fma2(unsigned long long& d,
                                     unsigned long long a, unsigned long long b) {
    asm("fma.rn.f32x2 %0, %1, %2, %0;" : "+l"(d) : "l"(a), "l"(b));
}
__device__ __forceinline__ float2 unpack2(unsigned long long a) {
    float2 f;
    asm("mov.b64 {%0, %1}, %2;" : "=f"(f.x), "=f"(f.y) : "l"(a));
    return f;
}
__device__ __forceinline__ void cp16(unsigned dst, const void* src) {
    asm volatile("cp.async.cg.shared.global [%0], [%1], 16;" :: "r"(dst), "l"(src));
}
#define CP_COMMIT() asm volatile("cp.async.commit_group;")
#define CP_WAIT1()  asm volatile("cp.async.wait_group 1;")
#define CP_WAIT0()  asm volatile("cp.async.wait_group 0;")

__device__ __forceinline__ void mma16816(float* c, unsigned a0, unsigned a1,
                                         unsigned a2, unsigned a3,
                                         unsigned b0, unsigned b1) {
    asm volatile(
        "mma.sync.aligned.m16n8k16.row.col.f32.f16.f16.f32 "
        "{%0,%1,%2,%3}, {%4,%5,%6,%7}, {%8,%9}, {%0,%1,%2,%3};"
        : "+f"(c[0]), "+f"(c[1]), "+f"(c[2]), "+f"(c[3])
        : "r"(a0), "r"(a1), "r"(a2), "r"(a3), "r"(b0), "r"(b1));
}

// e-pass term with register-resident wq/v (8 fp16 elems)
__device__ __forceinline__ float row_term_r(uint4 u, float4 q0, float4 q1,
                                            float4 v0, float4 v1) {
    float2 f0 = __half22float2(*(__half2*)&u.x);
    float2 f1 = __half22float2(*(__half2*)&u.y);
    float2 f2 = __half22float2(*(__half2*)&u.z);
    float2 f3 = __half22float2(*(__half2*)&u.w);
    float a;
    a  = v0.x * tanh_fast(f0.x + q0.x);
    a += v0.y * tanh_fast(f0.y + q0.y);
    a += v0.z * tanh_fast(f1.x + q0.z);
    a += v0.w * tanh_fast(f1.y + q0.w);
    a += v1.x * tanh_fast(f2.x + q1.x);
    a += v1.y * tanh_fast(f2.y + q1.y);
    a += v1.z * tanh_fast(f3.x + q1.z);
    a += v1.w * tanh_fast(f3.y + q1.w);
    return a;
}

// sense-reversing grid barrier
__device__ __forceinline__ void gsync() {
    __syncthreads();
    if (threadIdx.x == 0) {
        volatile unsigned* genp = (volatile unsigned*)&g_bar_gen;
        unsigned gen = *genp;
        __threadfence();
        if (atomicAdd(&g_bar_count, 1u) == (unsigned)(GBLK - 1)) {
            g_bar_count = 0;
            __threadfence();
            *genp = gen + 1;
        } else {
            while (*genp == gen) { }
            __threadfence();
        }
    }
    __syncthreads();
}

// ------------------- the single persistent kernel -------------------
__global__ void __launch_bounds__(256, 2)
k_decoder(const float* __restrict__ H,  const float* __restrict__ d0,
          const float* __restrict__ s0, const float* __restrict__ W_d,
          const float* __restrict__ U_d, const float* __restrict__ v_d,
          const float* __restrict__ W_ih, const float* __restrict__ W_hh,
          const float* __restrict__ b_ih, const float* __restrict__ b_hh,
          float* __restrict__ out) {
    __shared__ __align__(16) float sm[12288];   // 48 KB, unioned per phase
    __half* sbuf = (__half*)sm;

    const int tid  = threadIdx.x;
    const int bid  = blockIdx.x;
    const int gtid = bid * 256 + tid;
    const int nthr = GBLK * 256;
    const int w = tid >> 5, lane = tid & 31;    // 8 warps per block

    unsigned sb_u32;
    {   unsigned long long g = __cvta_generic_to_shared(sm);
        sb_u32 = (unsigned)g; }

    // ---------------- preamble ----------------
    for (int i = gtid; i < 524288; i += nthr)              // W_d fp16, native [n][k]
        g_WdTh[i] = __float2half_rn(W_d[i]);
    for (int i = gtid; i < 262144; i += nthr) {            // U_d -> UdT[m][n]
        int n = i >> 9, m = i & 511;
        g_UdT[m * 512 + n] = U_d[i];
    }
    for (int i = gtid; i < 1048576; i += nthr) {           // fused W fp16, permuted rows
        int row = i >> 9, m = i & 511;
        int gate = row >> 9, p = row & 511;
        int np = p * 4 + gate;
        g_Wh[(size_t)np * 1024 + m]       = __float2half_rn(W_ih[i]);
        g_Wh[(size_t)np * 1024 + 512 + m] = __float2half_rn(W_hh[i]);
    }
    for (int i = gtid; i < 2048; i += nthr) {              // permuted bias
        int gate = i >> 9, p = i & 511;
        g_bias[p * 4 + gate] = b_ih[i] + b_hh[i];
    }
    for (int i = gtid; i < 131072; i += nthr) {            // state init
        int b = i >> 9, p = i & 511;
        g_qhA[b * 1024 + p]       = __float2half_rn(d0[i]);
        g_qhA[b * 1024 + 512 + p] = __float2half_rn(s0[i]);
        g_s[i] = s0[i];
    }
    for (int i = gtid; i < 8388608; i += nthr) {           // H -> fp16
        float4 h4 = *(const float4*)&H[(size_t)i * 4];
        *(__half2*)&g_Hh[(size_t)i * 4]     = __floats2half2_rn(h4.x, h4.y);
        *(__half2*)&g_Hh[(size_t)i * 4 + 2] = __floats2half2_rn(h4.z, h4.w);
    }
    gsync();

    // ---------------- phase U: UH = H @ UdT (fp16 out), 32 tiles/block ----------------
    for (int it = 0; it < 32; it++) {
        const int i0 = (bid * 32 + it) * 8;
        __syncthreads();
        for (int idx = tid; idx < 4096; idx += 256) {
            int m = idx & 511, r = idx >> 9;
            sm[m * 12 + r] = H[(size_t)(i0 + r) * 512 + m];
        }
        __syncthreads();

        const int c0 = tid * 2;
        unsigned long long acc0[4] = {0, 0, 0, 0};
        unsigned long long acc1[4] = {0, 0, 0, 0};
#pragma unroll 4
        for (int m = 0; m < 512; m++) {
            float2 wv = *(const float2*)&g_UdT[m * 512 + c0];
            unsigned long long w0 = pack2(wv.x), w1 = pack2(wv.y);
            const float* hr = &sm[m * 12];
            ulonglong2 h01 = *(const ulonglong2*)&hr[0];
            ulonglong2 h23 = *(const ulonglong2*)&hr[4];
            fma2(acc0[0], w0, h01.x); fma2(acc1[0], w1, h01.x);
            fma2(acc0[1], w0, h01.y); fma2(acc1[1], w1, h01.y);
            fma2(acc0[2], w0, h23.x); fma2(acc1[2], w1, h23.x);
            fma2(acc0[3], w0, h23.y); fma2(acc1[3], w1, h23.y);
        }
#pragma unroll
        for (int rp = 0; rp < 4; rp++) {
            float2 a0 = unpack2(acc0[rp]);
            float2 a1 = unpack2(acc1[rp]);
            *(__half2*)&g_UHh[(size_t)(i0 + 2 * rp) * 512 + c0]     = __floats2half2_rn(a0.x, a1.x);
            *(__half2*)&g_UHh[(size_t)(i0 + 2 * rp + 1) * 512 + c0] = __floats2half2_rn(a0.y, a1.y);
        }
    }
    gsync();

    // ---------------- main scan: 256 steps, 3 barriers each ----------------
    for (int step = 0; step < 256; ++step) {
        const __half* qh_cur = (step & 1) ? g_qhB : g_qhA;
        __half*       qh_nxt = (step & 1) ? g_qhA : g_qhB;

        // ==== P1: wq GEMM via mma. tile = 32 batches x 64 cols x 256 k (quarter) ====
        {
            const int mg = bid >> 5;
            const int ng = (bid >> 2) & 7;
            const int kq = bid & 3;
            const int b_base = mg * 32;
            const int wm = w & 1, wn = w >> 1;
            const int m_off = wm * 16, n_off = wn * 16;
            const int tq = lane >> 2, tr = lane & 3;

            __half* Ab[2] = { sbuf, sbuf + 2304 };
            __half* Bb[2] = { sbuf + 4608, sbuf + 9216 };
            const unsigned A_u32[2] = { sb_u32, sb_u32 + 4608 };
            const unsigned B_u32[2] = { sb_u32 + 9216, sb_u32 + 18432 };

            float acc0[4] = {0.f, 0.f, 0.f, 0.f};
            float acc1[4] = {0.f, 0.f, 0.f, 0.f};

            {
                const int rowA = tid >> 3, segA = tid & 7;
                cp16(A_u32[0] + (rowA * 72 + segA * 8) * 2,
                     &qh_cur[(b_base + rowA) * 1024 + kq * 256 + segA * 8]);
#pragma unroll
                for (int j = 0; j < 2; j++) {
                    int idx = tid + j * 256;
                    int nB = idx >> 3, segB = idx & 7;
                    cp16(B_u32[0] + (nB * 72 + segB * 8) * 2,
                         &g_WdTh[(size_t)(ng * 64 + nB) * 1024 + kq * 256 + segB * 8]);
                }
                CP_COMMIT();
            }
            for (int ch = 0; ch < 4; ch++) {
                if (ch < 3) {
                    const int nc = ch + 1, buf = nc & 1;
                    const int rowA = tid >> 3, segA = tid & 7;
                    cp16(A_u32[buf] + (rowA * 72 + segA * 8) * 2,
                         &qh_cur[(b_base + rowA) * 1024 + kq * 256 + nc * 64 + segA * 8]);
#pragma unroll
                    for (int j = 0; j < 2; j++) {
                        int idx = tid + j * 256;
                        int nB = idx >> 3, segB = idx & 7;
                        cp16(B_u32[buf] + (nB * 72 + segB * 8) * 2,
                             &g_WdTh[(size_t)(ng * 64 + nB) * 1024
                                     + kq * 256 + nc * 64 + segB * 8]);
                    }
                    CP_COMMIT();
                    CP_WAIT1();
                } else {
                    CP_WAIT0();
                }
                __syncthreads();

                const __half* A = Ab[ch & 1];
                const __half* B = Bb[ch & 1];
#pragma unroll
                for (int ks = 0; ks < 4; ks++) {
                    const int kc = ks * 16 + tr * 2;
                    unsigned a0 = *(const unsigned*)&A[(m_off + tq) * 72 + kc];
                    unsigned a1 = *(const unsigned*)&A[(m_off + tq + 8) * 72 + kc];
                    unsigned a2 = *(const unsigned*)&A[(m_off + tq) * 72 + kc + 8];
                    unsigned a3 = *(const unsigned*)&A[(m_off + tq + 8) * 72 + kc + 8];
                    unsigned b0 = *(const unsigned*)&B[(n_off + tq) * 72 + kc];
                    unsigned b1 = *(const unsigned*)&B[(n_off + tq) * 72 + kc + 8];
                    unsigned b2 = *(const unsigned*)&B[(n_off + 8 + tq) * 72 + kc];
                    unsigned b3 = *(const unsigned*)&B[(n_off + 8 + tq) * 72 + kc + 8];
                    mma16816(acc0, a0, a1, a2, a3, b0, b1);
                    mma16816(acc1, a0, a1, a2, a3, b2, b3);
                }
                __syncthreads();
            }

            float* dst = &g_wqp[kq * 131072];
            const int row0 = b_base + m_off + tq, row1 = row0 + 8;
            const int col0 = ng * 64 + n_off + tr * 2;
            *(float2*)&dst[row0 * 512 + col0]     = make_float2(acc0[0], acc0[1]);
            *(float2*)&dst[row1 * 512 + col0]     = make_float2(acc0[2], acc0[3]);
            *(float2*)&dst[row0 * 512 + col0 + 8] = make_float2(acc1[0], acc1[1]);
            *(float2*)&dst[row1 * 512 + col0 + 8] = make_float2(acc1[2], acc1[3]);
            __syncthreads();
        }
        gsync();

        // ==== P2: warp-private streamed e -> softmax -> attn -> ct. block = batch ====
        // 8 warps x 32 rows each; per-warp stream region = 2 slots x 1024 B.
        {
            const int b = bid;
            float* wqs  = sm + 8192;     // 512
            float* vs   = sm + 8704;     // 512
            float* es   = sm + 9216;     // 256
            float* beta = sm + 9472;     // 256
            float* red8 = sm + 9728;     // 8
            for (int i = tid; i < 512; i += 256) {
                wqs[i] = ((g_wqp[b * 512 + i] + g_wqp[131072 + b * 512 + i])
                          + g_wqp[262144 + b * 512 + i]) + g_wqp[393216 + b * 512 + i];
                vs[i] = v_d[i];
            }
            __syncthreads();

            // lane owns cols [lane*16, lane*16+16)
            const float4 qa0 = *(const float4*)&wqs[lane * 16];
            const float4 qa1 = *(const float4*)&wqs[lane * 16 + 4];
            const float4 qa2 = *(const float4*)&wqs[lane * 16 + 8];
            const float4 qa3 = *(const float4*)&wqs[lane * 16 + 12];
            const float4 va0 = *(const float4*)&vs[lane * 16];
            const float4 va1 = *(const float4*)&vs[lane * 16 + 4];
            const float4 va2 = *(const float4*)&vs[lane * 16 + 8];
            const float4 va3 = *(const float4*)&vs[lane * 16 + 12];

            // warp-private stream region: 2 slots x 512 halves (2048 B per warp)
            __half* wbuf = sbuf + w * 1024;
            const unsigned wbuf_u32 = sb_u32 + w * 2048;

            // ---- e-pass: warp w streams rows w*32 .. w*32+31, zero block syncs ----
            {
                const __half* uh = g_UHh + (size_t)b * 131072 + (size_t)(w * 32) * 512;
                cp16(wbuf_u32 + lane * 32, uh + lane * 16);
                cp16(wbuf_u32 + lane * 32 + 16, uh + lane * 16 + 8);
                CP_COMMIT();
#pragma unroll 4
                for (int r = 0; r < 32; r++) {
                    if (r < 31) {
                        const __half* src = uh + (r + 1) * 512 + lane * 16;
                        const unsigned dst = wbuf_u32 + ((r + 1) & 1) * 1024 + lane * 32;
                        cp16(dst, src);
                        cp16(dst + 16, src + 8);
                        CP_COMMIT();
                        CP_WAIT1();
                    } else {
                        CP_WAIT0();
                    }
                    __syncwarp();
                    const __half* row = wbuf + (r & 1) * 512;
                    uint4 u0 = *(const uint4*)(row + lane * 16);
                    uint4 u1 = *(const uint4*)(row + lane * 16 + 8);
                    float e = row_term_r(u0, qa0, qa1, va0, va1)
                            + row_term_r(u1, qa2, qa3, va2, va3);
#pragma unroll
                    for (int off = 16; off; off >>= 1)
                        e += __shfl_xor_sync(0xffffffffu, e, off);
                    if (lane == 0) es[w * 32 + r] = e;
                    __syncwarp();
                }
            }
            __syncthreads();

            // ---- softmax + attn write ----
            {
                float ev = es[tid];
                float mv = ev;
#pragma unroll
                for (int off = 16; off; off >>= 1)
                    mv = fmaxf(mv, __shfl_xor_sync(0xffffffffu, mv, off));
                if (lane == 0) red8[w] = mv;
                __syncthreads();
                float bm = red8[0];
#pragma unroll
                for (int i = 1; i < 8; i++) bm = fmaxf(bm, red8[i]);
                float ex = __expf(ev - bm);
                float sv = ex;
#pragma unroll
                for (int off = 16; off; off >>= 1)
                    sv += __shfl_xor_sync(0xffffffffu, sv, off);
                __syncthreads();
                if (lane == 0) red8[w] = sv;
                __syncthreads();
                float bs = 0.f;
#pragma unroll
                for (int i = 0; i < 8; i++) bs += red8[i];
                float bt = ex / bs;
                beta[tid] = bt;
                out[(size_t)ATTN_OFF + (size_t)b * 65536
                    + (size_t)step * 256 + tid] = bt;
            }
            __syncthreads();

            // ---- ct-pass: warp-private stream over H rows w*32..w*32+31 ----
            {
                const __half* hb = g_Hh + (size_t)b * 131072 + (size_t)(w * 32) * 512;
                float acc[16];
#pragma unroll
                for (int i = 0; i < 16; i++) acc[i] = 0.f;

                cp16(wbuf_u32 + lane * 32, hb + lane * 16);
                cp16(wbuf_u32 + lane * 32 + 16, hb + lane * 16 + 8);
                CP_COMMIT();
#pragma unroll 4
                for (int r = 0; r < 32; r++) {
                    if (r < 31) {
                        const __half* src = hb + (r + 1) * 512 + lane * 16;
                        const unsigned dst = wbuf_u32 + ((r + 1) & 1) * 1024 + lane * 32;
                        cp16(dst, src);
                        cp16(dst + 16, src + 8);
                        CP_COMMIT();
                        CP_WAIT1();
                    } else {
                        CP_WAIT0();
                    }
                    __syncwarp();
                    const __half* row = wbuf + (r & 1) * 512;
                    uint4 u0 = *(const uint4*)(row + lane * 16);
                    uint4 u1 = *(const uint4*)(row + lane * 16 + 8);
                    const float bv = beta[w * 32 + r];
                    float2 h;
                    h = __half22float2(*(__half2*)&u0.x); acc[0] += bv*h.x;  acc[1] += bv*h.y;
                    h = __half22float2(*(__half2*)&u0.y); acc[2] += bv*h.x;  acc[3] += bv*h.y;
                    h = __half22float2(*(__half2*)&u0.z); acc[4] += bv*h.x;  acc[5] += bv*h.y;
                    h = __half22float2(*(__half2*)&u0.w); acc[6] += bv*h.x;  acc[7] += bv*h.y;
                    h = __half22float2(*(__half2*)&u1.x); acc[8] += bv*h.x;  acc[9] += bv*h.y;
                    h = __half22float2(*(__half2*)&u1.y); acc[10] += bv*h.x; acc[11] += bv*h.y;
                    h = __half22float2(*(__half2*)&u1.z); acc[12] += bv*h.x; acc[13] += bv*h.y;
                    h = __half22float2(*(__half2*)&u1.w); acc[14] += bv*h.x; acc[15] += bv*h.y;
                    __syncwarp();
                }
                // per-warp partial into the warp's own (finished) stream region
                float* part = sm + w * 512 + lane * 16;
#pragma unroll
                for (int i = 0; i < 16; i += 4)
                    *(float4*)&part[i] = make_float4(acc[i], acc[i+1], acc[i+2], acc[i+3]);
            }
            __syncthreads();
            // final 8-way reduce: thread owns cols 2*tid, 2*tid+1
            {
                const int c0 = tid * 2;
                float s0 = 0.f, s1 = 0.f;
#pragma unroll
                for (int ww = 0; ww < 8; ww++) {
                    float2 p = *(const float2*)&sm[ww * 512 + c0];
                    s0 += p.x; s1 += p.y;
                }
                *(float2*)&g_ct[b * 512 + c0] = make_float2(s0, s1);
                *(__half2*)&g_qct[b * 512 + c0] = __floats2half2_rn(s0, s1);
            }
        }
        gsync();

        // ==== P3: gates GEMM via tensor cores + fused LSTM epilogue ====
        {
            const int bg = bid >> 5;
            const int cg = bid & 31;
            const int b_base = bg * 32;
            const int wm = w & 1, wn = w >> 1;
            const int m_off = wm * 16, n_off = wn * 16;
            const int tq = lane >> 2, tr = lane & 3;

            __half* Ab[2] = { sbuf, sbuf + 2304 };
            __half* Bb[2] = { sbuf + 4608, sbuf + 9216 };
            const unsigned A_u32[2] = { sb_u32, sb_u32 + 4608 };
            const unsigned B_u32[2] = { sb_u32 + 9216, sb_u32 + 18432 };

            float acc0[4] = {0.f, 0.f, 0.f, 0.f};
            float acc1[4] = {0.f, 0.f, 0.f, 0.f};

            {
                const int rowA = tid >> 3, segA = tid & 7;
                cp16(A_u32[0] + (rowA * 72 + segA * 8) * 2,
                     &g_qct[(b_base + rowA) * 512 + segA * 8]);
#pragma unroll
                for (int j = 0; j < 2; j++) {
                    int idx = tid + j * 256;
                    int nB = idx >> 3, segB = idx & 7;
                    cp16(B_u32[0] + (nB * 72 + segB * 8) * 2,
                         &g_Wh[(size_t)(cg * 64 + nB) * 1024 + segB * 8]);
                }
                CP_COMMIT();
            }
            for (int ch = 0; ch < 16; ch++) {
                if (ch < 15) {
                    const int nc = ch + 1, buf = nc & 1;
                    const int kbase = (nc & 7) * 64;
                    const int rowA = tid >> 3, segA = tid & 7;
                    const __half* srcA = (nc < 8)
                        ? &g_qct[(b_base + rowA) * 512 + kbase + segA * 8]
                        : &qh_cur[(b_base + rowA) * 1024 + kbase + segA * 8];
                    cp16(A_u32[buf] + (rowA * 72 + segA * 8) * 2, srcA);
#pragma unroll
                    for (int j = 0; j < 2; j++) {
                        int idx = tid + j * 256;
                        int nB = idx >> 3, segB = idx & 7;
                        cp16(B_u32[buf] + (nB * 72 + segB * 8) * 2,
                             &g_Wh[(size_t)(cg * 64 + nB) * 1024 + nc * 64 + segB * 8]);
                    }
                    CP_COMMIT();
                    CP_WAIT1();
                } else {
                    CP_WAIT0();
                }
                __syncthreads();

                const __half* A = Ab[ch & 1];
                const __half* B = Bb[ch & 1];
#pragma unroll
                for (int ks = 0; ks < 4; ks++) {
                    const int kc = ks * 16 + tr * 2;
                    unsigned a0 = *(const unsigned*)&A[(m_off + tq) * 72 + kc];
                    unsigned a1 = *(const unsigned*)&A[(m_off + tq + 8) * 72 + kc];
                    unsigned a2 = *(const unsigned*)&A[(m_off + tq) * 72 + kc + 8];
                    unsigned a3 = *(const unsigned*)&A[(m_off + tq + 8) * 72 + kc + 8];
                    unsigned b0 = *(const unsigned*)&B[(n_off + tq) * 72 + kc];
                    unsigned b1 = *(const unsigned*)&B[(n_off + tq) * 72 + kc + 8];
                    unsigned b2 = *(const unsigned*)&B[(n_off + 8 + tq) * 72 + kc];
                    unsigned b3 = *(const unsigned*)&B[(n_off + 8 + tq) * 72 + kc + 8];
                    mma16816(acc0, a0, a1, a2, a3, b0, b1);
                    mma16816(acc1, a0, a1, a2, a3, b2, b3);
                }
                __syncthreads();
            }

            // epilogue: gather gates via lane-pair shfl, fused LSTM
#pragma unroll
            for (int t = 0; t < 2; t++) {
                const float* a = t ? acc1 : acc0;
                float pg0 = __shfl_sync(0xffffffffu, a[0], lane | 1);
                float po0 = __shfl_sync(0xffffffffu, a[1], lane | 1);
                float pg1 = __shfl_sync(0xffffffffu, a[2], lane | 1);
                float po1 = __shfl_sync(0xffffffffu, a[3], lane | 1);
                if ((lane & 1) == 0) {
                    const int u = cg * 16 + wn * 4 + t * 2 + (tr >> 1);
                    const float4 bi4 = *(const float4*)&g_bias[u * 4];
                    const int row0 = b_base + m_off + tq;
                    const int row1 = row0 + 8;
                    {
                        float iv = a[0] + bi4.x, fv = a[1] + bi4.y;
                        float gv = pg0 + bi4.z,  ov = po0 + bi4.w;
                        float s_new = sigmoid_fast(fv) * g_s[row0 * 512 + u]
                                    + sigmoid_fast(iv) * tanh_fast(gv);
                        float d_new = sigmoid_fast(ov) * tanh_fast(s_new);
                        g_s[row0 * 512 + u] = s_new;
                        qh_nxt[row0 * 1024 + u]       = __float2half_rn(d_new);
                        qh_nxt[row0 * 1024 + 512 + u] = __float2half_rn(s_new);
                        g_dout[row0 * 512 + u] = d_new;
                    }
                    {
                        float iv = a[2] + bi4.x, fv = a[3] + bi4.y;
                        float gv = pg1 + bi4.z,  ov = po1 + bi4.w;
                        float s_new = sigmoid_fast(fv) * g_s[row1 * 512 + u]
                                    + sigmoid_fast(iv) * tanh_fast(gv);
                        float d_new = sigmoid_fast(ov) * tanh_fast(s_new);
                        g_s[row1 * 512 + u] = s_new;
                        qh_nxt[row1 * 1024 + u]       = __float2half_rn(d_new);
                        qh_nxt[row1 * 1024 + 512 + u] = __float2half_rn(s_new);
                        g_dout[row1 * 512 + u] = d_new;
                    }
                }
            }
            __syncthreads();
        }
        gsync();
    }

    // ---------------- epilogue: out head = [d_final ; ct_last] ----------------
    for (int i = gtid; i < 262144; i += nthr) {
        int b = i >> 10, j = i & 1023;
        out[i] = (j < 512) ? g_dout[b * 512 + j] : g_ct[b * 512 + (j - 512)];
    }
}

// ------------------- launch -------------------
extern "C" void kernel_launch(void* const* d_in, const int* in_sizes, int n_in,
                              void* d_out, int out_size) {
    (void)in_sizes; (void)n_in; (void)out_size;
    const float* H    = (const float*)d_in[0];
    const float* d0   = (const float*)d_in[1];
    const float* s0   = (const float*)d_in[2];
    const float* W_d  = (const float*)d_in[3];
    const float* U_d  = (const float*)d_in[4];
    const float* v_d  = (const float*)d_in[5];
    const float* W_ih = (const float*)d_in[6];
    const float* W_hh = (const float*)d_in[7];
    const float* b_ih = (const float*)d_in[8];
    const float* b_hh = (const float*)d_in[9];
    float* out = (float*)d_out;

    k_decoder<<<GBLK, 256>>>(H, d0, s0, W_d, U_d, v_d, W_ih, W_hh, b_ih, b_hh, out);
}

// round 16
// speedup vs baseline: 1.1307x; 1.1307x over previous
#include <cuda_runtime.h>
#include <cuda_fp16.h>
#include <math.h>

#define ATTN_OFF 262144          // B*1024 head elems, then attn [B,T,T]
#define GBLK 256                 // 256 blocks x 256 threads, 2 per SM

// ------------------- device globals (no allocation allowed) -------------------
__device__ __half g_UHh [33554432];        // [B*T, M] fp16 (67 MB)
__device__ __half g_Hh  [33554432];        // fp16 copy of H (67 MB)
__device__ __half g_WdTh[512 * 1024];      // W_d fp16, native [n=512][k=1024] (mma B layout)
__device__ __half g_Udh [512 * 512];       // U_d fp16, native [n=512][m=512] (mma B layout)
__device__ __half g_Wh  [2048 * 1024];     // fused W fp16, rows = permuted n' = p*4+gate
__device__ float  g_bias[2048];            // (b_ih+b_hh) permuted [p*4+gate]
__device__ __half g_qhA [256 * 1024];      // state [d(512); s(512)] fp16, ping
__device__ __half g_qhB [256 * 1024];      // state pong
__device__ __half g_qct [256 * 512];       // ct fp16
__device__ float  g_s   [131072];          // cell state fp32
__device__ float  g_dout[131072];          // d fp32 (for out head)
__device__ float  g_ct  [131072];          // ct fp32 (for out head)
__device__ float  g_wqp [4 * 131072];      // 4 k-quarter partials of wq

__device__ unsigned g_bar_count = 0;
__device__ unsigned g_bar_gen   = 0;

// ------------------- helpers -------------------
__device__ __forceinline__ float tanh_fast(float x) {
    float y;
    asm("tanh.approx.f32 %0, %1;" : "=f"(y) : "f"(x));
    return y;
}
__device__ __forceinline__ float sigmoid_fast(float x) {
    return 1.f / (1.f + __expf(-x));
}
__device__ __forceinline__ void cp16(unsigned dst, const void* src) {
    asm volatile("cp.async.cg.shared.global [%0], [%1], 16;" :: "r"(dst), "l"(src));
}
#define CP_COMMIT() asm volatile("cp.async.commit_group;")
#define CP_WAIT1()  asm volatile("cp.async.wait_group 1;")
#define CP_WAIT0()  asm volatile("cp.async.wait_group 0;")

__device__ __forceinline__ void mma16816(float* c, unsigned a0, unsigned a1,
                                         unsigned a2, unsigned a3,
                                         unsigned b0, unsigned b1) {
    asm volatile(
        "mma.sync.aligned.m16n8k16.row.col.f32.f16.f16.f32 "
        "{%0,%1,%2,%3}, {%4,%5,%6,%7}, {%8,%9}, {%0,%1,%2,%3};"
        : "+f"(c[0]), "+f"(c[1]), "+f"(c[2]), "+f"(c[3])
        : "r"(a0), "r"(a1), "r"(a2), "r"(a3), "r"(b0), "r"(b1));
}

// e-pass term with register-resident wq/v
__device__ __forceinline__ float row_term_r(uint4 u, float4 q0, float4 q1,
                                            float4 v0, float4 v1) {
    float2 f0 = __half22float2(*(__half2*)&u.x);
    float2 f1 = __half22float2(*(__half2*)&u.y);
    float2 f2 = __half22float2(*(__half2*)&u.z);
    float2 f3 = __half22float2(*(__half2*)&u.w);
    float a;
    a  = v0.x * tanh_fast(f0.x + q0.x);
    a += v0.y * tanh_fast(f0.y + q0.y);
    a += v0.z * tanh_fast(f1.x + q0.z);
    a += v0.w * tanh_fast(f1.y + q0.w);
    a += v1.x * tanh_fast(f2.x + q1.x);
    a += v1.y * tanh_fast(f2.y + q1.y);
    a += v1.z * tanh_fast(f3.x + q1.z);
    a += v1.w * tanh_fast(f3.y + q1.w);
    return a;
}

// sense-reversing grid barrier
__device__ __forceinline__ void gsync() {
    __syncthreads();
    if (threadIdx.x == 0) {
        volatile unsigned* genp = (volatile unsigned*)&g_bar_gen;
        unsigned gen = *genp;
        __threadfence();
        if (atomicAdd(&g_bar_count, 1u) == (unsigned)(GBLK - 1)) {
            g_bar_count = 0;
            __threadfence();
            *genp = gen + 1;
        } else {
            while (*genp == gen) { }
            __threadfence();
        }
    }
    __syncthreads();
}

// ------------------- the single persistent kernel -------------------
__global__ void __launch_bounds__(256, 2)
k_decoder(const float* __restrict__ H,  const float* __restrict__ d0,
          const float* __restrict__ s0, const float* __restrict__ W_d,
          const float* __restrict__ U_d, const float* __restrict__ v_d,
          const float* __restrict__ W_ih, const float* __restrict__ W_hh,
          const float* __restrict__ b_ih, const float* __restrict__ b_hh,
          float* __restrict__ out) {
    __shared__ __align__(16) float sm[12288];   // 48 KB, unioned per phase
    __half* sbuf = (__half*)sm;

    const int tid  = threadIdx.x;
    const int bid  = blockIdx.x;
    const int gtid = bid * 256 + tid;
    const int nthr = GBLK * 256;
    const int w = tid >> 5, lane = tid & 31;

    unsigned sb_u32;
    {   unsigned long long g = __cvta_generic_to_shared(sm);
        sb_u32 = (unsigned)g; }

    // ---------------- preamble ----------------
    for (int i = gtid; i < 524288; i += nthr)              // W_d fp16, native [n][k]
        g_WdTh[i] = __float2half_rn(W_d[i]);
    for (int i = gtid; i < 262144; i += nthr)              // U_d fp16, native [n][m]
        g_Udh[i] = __float2half_rn(U_d[i]);
    for (int i = gtid; i < 1048576; i += nthr) {           // fused W fp16, permuted rows
        int row = i >> 9, m = i & 511;
        int gate = row >> 9, p = row & 511;
        int np = p * 4 + gate;
        g_Wh[(size_t)np * 1024 + m]       = __float2half_rn(W_ih[i]);
        g_Wh[(size_t)np * 1024 + 512 + m] = __float2half_rn(W_hh[i]);
    }
    for (int i = gtid; i < 2048; i += nthr) {              // permuted bias
        int gate = i >> 9, p = i & 511;
        g_bias[p * 4 + gate] = b_ih[i] + b_hh[i];
    }
    for (int i = gtid; i < 131072; i += nthr) {            // state init
        int b = i >> 9, p = i & 511;
        g_qhA[b * 1024 + p]       = __float2half_rn(d0[i]);
        g_qhA[b * 1024 + 512 + p] = __float2half_rn(s0[i]);
        g_s[i] = s0[i];
    }
    for (int i = gtid; i < 8388608; i += nthr) {           // H -> fp16
        float4 h4 = *(const float4*)&H[(size_t)i * 4];
        *(__half2*)&g_Hh[(size_t)i * 4]     = __floats2half2_rn(h4.x, h4.y);
        *(__half2*)&g_Hh[(size_t)i * 4 + 2] = __floats2half2_rn(h4.z, h4.w);
    }
    gsync();

    // ---------------- phase U: UH = Hh @ Udh^T via mma. 64 tiles/block ----------------
    // tile = 32 rows x 64 cols x K=512 (8 chunks of 64)
    {
        const int wm = w & 1, wn = w >> 1;
        const int m_off = wm * 16, n_off = wn * 16;
        const int tq = lane >> 2, tr = lane & 3;

        __half* Ab[2] = { sbuf, sbuf + 2304 };
        __half* Bb[2] = { sbuf + 4608, sbuf + 9216 };
        const unsigned A_u32[2] = { sb_u32, sb_u32 + 4608 };
        const unsigned B_u32[2] = { sb_u32 + 9216, sb_u32 + 18432 };

        for (int it = 0; it < 64; it++) {
            const int tile = bid * 64 + it;
            const int mg = tile >> 3, ng = tile & 7;
            const size_t r_base = (size_t)mg * 32;

            float acc0[4] = {0.f, 0.f, 0.f, 0.f};
            float acc1[4] = {0.f, 0.f, 0.f, 0.f};

            {
                const int rowA = tid >> 3, segA = tid & 7;
                cp16(A_u32[0] + (rowA * 72 + segA * 8) * 2,
                     &g_Hh[(r_base + rowA) * 512 + segA * 8]);
#pragma unroll
                for (int j = 0; j < 2; j++) {
                    int idx = tid + j * 256;
                    int nB = idx >> 3, segB = idx & 7;
                    cp16(B_u32[0] + (nB * 72 + segB * 8) * 2,
                         &g_Udh[(size_t)(ng * 64 + nB) * 512 + segB * 8]);
                }
                CP_COMMIT();
            }
            for (int ch = 0; ch < 8; ch++) {
                if (ch < 7) {
                    const int nc = ch + 1, buf = nc & 1;
                    const int rowA = tid >> 3, segA = tid & 7;
                    cp16(A_u32[buf] + (rowA * 72 + segA * 8) * 2,
                         &g_Hh[(r_base + rowA) * 512 + nc * 64 + segA * 8]);
#pragma unroll
                    for (int j = 0; j < 2; j++) {
                        int idx = tid + j * 256;
                        int nB = idx >> 3, segB = idx & 7;
                        cp16(B_u32[buf] + (nB * 72 + segB * 8) * 2,
                             &g_Udh[(size_t)(ng * 64 + nB) * 512 + nc * 64 + segB * 8]);
                    }
                    CP_COMMIT();
                    CP_WAIT1();
                } else {
                    CP_WAIT0();
                }
                __syncthreads();

                const __half* A = Ab[ch & 1];
                const __half* B = Bb[ch & 1];
#pragma unroll
                for (int ks = 0; ks < 4; ks++) {
                    const int kc = ks * 16 + tr * 2;
                    unsigned a0 = *(const unsigned*)&A[(m_off + tq) * 72 + kc];
                    unsigned a1 = *(const unsigned*)&A[(m_off + tq + 8) * 72 + kc];
                    unsigned a2 = *(const unsigned*)&A[(m_off + tq) * 72 + kc + 8];
                    unsigned a3 = *(const unsigned*)&A[(m_off + tq + 8) * 72 + kc + 8];
                    unsigned b0 = *(const unsigned*)&B[(n_off + tq) * 72 + kc];
                    unsigned b1 = *(const unsigned*)&B[(n_off + tq) * 72 + kc + 8];
                    unsigned b2 = *(const unsigned*)&B[(n_off + 8 + tq) * 72 + kc];
                    unsigned b3 = *(const unsigned*)&B[(n_off + 8 + tq) * 72 + kc + 8];
                    mma16816(acc0, a0, a1, a2, a3, b0, b1);
                    mma16816(acc1, a0, a1, a2, a3, b2, b3);
                }
                __syncthreads();
            }

            // epilogue: write fp16 UH
            const size_t row0 = r_base + m_off + tq, row1 = row0 + 8;
            const int col0 = ng * 64 + n_off + tr * 2;
            *(__half2*)&g_UHh[row0 * 512 + col0]     = __floats2half2_rn(acc0[0], acc0[1]);
            *(__half2*)&g_UHh[row1 * 512 + col0]     = __floats2half2_rn(acc0[2], acc0[3]);
            *(__half2*)&g_UHh[row0 * 512 + col0 + 8] = __floats2half2_rn(acc1[0], acc1[1]);
            *(__half2*)&g_UHh[row1 * 512 + col0 + 8] = __floats2half2_rn(acc1[2], acc1[3]);
        }
    }
    gsync();

    // ---------------- main scan: 256 steps, 3 barriers each ----------------
    for (int step = 0; step < 256; ++step) {
        const __half* qh_cur = (step & 1) ? g_qhB : g_qhA;
        __half*       qh_nxt = (step & 1) ? g_qhA : g_qhB;

        // ==== P1: wq GEMM via mma. tile = 32 batches x 64 cols x 256 k (quarter) ====
        {
            const int mg = bid >> 5;
            const int ng = (bid >> 2) & 7;
            const int kq = bid & 3;
            const int b_base = mg * 32;
            const int wm = w & 1, wn = w >> 1;
            const int m_off = wm * 16, n_off = wn * 16;
            const int tq = lane >> 2, tr = lane & 3;

            __half* Ab[2] = { sbuf, sbuf + 2304 };
            __half* Bb[2] = { sbuf + 4608, sbuf + 9216 };
            const unsigned A_u32[2] = { sb_u32, sb_u32 + 4608 };
            const unsigned B_u32[2] = { sb_u32 + 9216, sb_u32 + 18432 };

            float acc0[4] = {0.f, 0.f, 0.f, 0.f};
            float acc1[4] = {0.f, 0.f, 0.f, 0.f};

            {
                const int rowA = tid >> 3, segA = tid & 7;
                cp16(A_u32[0] + (rowA * 72 + segA * 8) * 2,
                     &qh_cur[(b_base + rowA) * 1024 + kq * 256 + segA * 8]);
#pragma unroll
                for (int j = 0; j < 2; j++) {
                    int idx = tid + j * 256;
                    int nB = idx >> 3, segB = idx & 7;
                    cp16(B_u32[0] + (nB * 72 + segB * 8) * 2,
                         &g_WdTh[(size_t)(ng * 64 + nB) * 1024 + kq * 256 + segB * 8]);
                }
                CP_COMMIT();
            }
            for (int ch = 0; ch < 4; ch++) {
                if (ch < 3) {
                    const int nc = ch + 1, buf = nc & 1;
                    const int rowA = tid >> 3, segA = tid & 7;
                    cp16(A_u32[buf] + (rowA * 72 + segA * 8) * 2,
                         &qh_cur[(b_base + rowA) * 1024 + kq * 256 + nc * 64 + segA * 8]);
#pragma unroll
                    for (int j = 0; j < 2; j++) {
                        int idx = tid + j * 256;
                        int nB = idx >> 3, segB = idx & 7;
                        cp16(B_u32[buf] + (nB * 72 + segB * 8) * 2,
                             &g_WdTh[(size_t)(ng * 64 + nB) * 1024
                                     + kq * 256 + nc * 64 + segB * 8]);
                    }
                    CP_COMMIT();
                    CP_WAIT1();
                } else {
                    CP_WAIT0();
                }
                __syncthreads();

                const __half* A = Ab[ch & 1];
                const __half* B = Bb[ch & 1];
#pragma unroll
                for (int ks = 0; ks < 4; ks++) {
                    const int kc = ks * 16 + tr * 2;
                    unsigned a0 = *(const unsigned*)&A[(m_off + tq) * 72 + kc];
                    unsigned a1 = *(const unsigned*)&A[(m_off + tq + 8) * 72 + kc];
                    unsigned a2 = *(const unsigned*)&A[(m_off + tq) * 72 + kc + 8];
                    unsigned a3 = *(const unsigned*)&A[(m_off + tq + 8) * 72 + kc + 8];
                    unsigned b0 = *(const unsigned*)&B[(n_off + tq) * 72 + kc];
                    unsigned b1 = *(const unsigned*)&B[(n_off + tq) * 72 + kc + 8];
                    unsigned b2 = *(const unsigned*)&B[(n_off + 8 + tq) * 72 + kc];
                    unsigned b3 = *(const unsigned*)&B[(n_off + 8 + tq) * 72 + kc + 8];
                    mma16816(acc0, a0, a1, a2, a3, b0, b1);
                    mma16816(acc1, a0, a1, a2, a3, b2, b3);
                }
                __syncthreads();
            }

            float* dst = &g_wqp[kq * 131072];
            const int row0 = b_base + m_off + tq, row1 = row0 + 8;
            const int col0 = ng * 64 + n_off + tr * 2;
            *(float2*)&dst[row0 * 512 + col0]     = make_float2(acc0[0], acc0[1]);
            *(float2*)&dst[row1 * 512 + col0]     = make_float2(acc0[2], acc0[3]);
            *(float2*)&dst[row0 * 512 + col0 + 8] = make_float2(acc1[0], acc1[1]);
            *(float2*)&dst[row1 * 512 + col0 + 8] = make_float2(acc1[2], acc1[3]);
            __syncthreads();
        }
        gsync();

        // ==== P2: cp.async-pipelined e -> softmax -> attn -> ct. block = batch ====
        {
            const int b = bid;
            float* wqs  = sm + 8192;
            float* vs   = sm + 8704;
            float* es   = sm + 9216;
            float* beta = sm + 9472;
            float* red8 = sm + 9728;
            for (int i = tid; i < 512; i += 256) {
                wqs[i] = ((g_wqp[b * 512 + i] + g_wqp[131072 + b * 512 + i])
                          + g_wqp[262144 + b * 512 + i]) + g_wqp[393216 + b * 512 + i];
                vs[i] = v_d[i];
            }
            __syncthreads();

            const float4 qa0 = *(const float4*)&wqs[lane * 8];
            const float4 qa1 = *(const float4*)&wqs[lane * 8 + 4];
            const float4 qb0 = *(const float4*)&wqs[256 + lane * 8];
            const float4 qb1 = *(const float4*)&wqs[256 + lane * 8 + 4];
            const float4 va0 = *(const float4*)&vs[lane * 8];
            const float4 va1 = *(const float4*)&vs[lane * 8 + 4];
            const float4 vb0 = *(const float4*)&vs[256 + lane * 8];
            const float4 vb1 = *(const float4*)&vs[256 + lane * 8 + 4];

            // ---- e-pass: stream UH rows, 16 chunks x 16 rows ----
            {
                const __half* uh = g_UHh + (size_t)b * 131072;
                {
                    const __half* src = uh + tid * 8;
                    unsigned dst = sb_u32 + tid * 16;
#pragma unroll
                    for (int j = 0; j < 4; j++)
                        cp16(dst + j * 4096, src + j * 2048);
                    CP_COMMIT();
                }
                for (int c = 0; c < 16; c++) {
                    if (c < 15) {
                        const __half* src = uh + (c + 1) * 8192 + tid * 8;
                        unsigned dst = sb_u32 + ((c + 1) & 1) * 16384 + tid * 16;
#pragma unroll
                        for (int j = 0; j < 4; j++)
                            cp16(dst + j * 4096, src + j * 2048);
                        CP_COMMIT();
                        CP_WAIT1();
                    } else {
                        CP_WAIT0();
                    }
                    __syncthreads();
                    const __half* base = sbuf + (c & 1) * 8192 + (w * 2) * 512;
                    uint4 a0 = *(const uint4*)(base + lane * 8);
                    uint4 a1 = *(const uint4*)(base + 256 + lane * 8);
                    uint4 b0v = *(const uint4*)(base + 512 + lane * 8);
                    uint4 b1v = *(const uint4*)(base + 768 + lane * 8);
                    float e0 = row_term_r(a0, qa0, qa1, va0, va1)
                             + row_term_r(a1, qb0, qb1, vb0, vb1);
                    float e1 = row_term_r(b0v, qa0, qa1, va0, va1)
                             + row_term_r(b1v, qb0, qb1, vb0, vb1);
#pragma unroll
                    for (int off = 16; off; off >>= 1) {
                        e0 += __shfl_xor_sync(0xffffffffu, e0, off);
                        e1 += __shfl_xor_sync(0xffffffffu, e1, off);
                    }
                    if (lane == 0) {
                        es[c * 16 + w * 2]     = e0;
                        es[c * 16 + w * 2 + 1] = e1;
                    }
                    __syncthreads();
                }
            }

            // ---- softmax + attn write ----
            {
                float ev = es[tid];
                float mv = ev;
#pragma unroll
                for (int off = 16; off; off >>= 1)
                    mv = fmaxf(mv, __shfl_xor_sync(0xffffffffu, mv, off));
                if (lane == 0) red8[w] = mv;
                __syncthreads();
                float bm = red8[0];
#pragma unroll
                for (int i = 1; i < 8; i++) bm = fmaxf(bm, red8[i]);
                float ex = __expf(ev - bm);
                float sv = ex;
#pragma unroll
                for (int off = 16; off; off >>= 1)
                    sv += __shfl_xor_sync(0xffffffffu, sv, off);
                __syncthreads();
                if (lane == 0) red8[w] = sv;
                __syncthreads();
                float bs = 0.f;
#pragma unroll
                for (int i = 0; i < 8; i++) bs += red8[i];
                float bt = ex / bs;
                beta[tid] = bt;
                out[(size_t)ATTN_OFF + (size_t)b * 65536
                    + (size_t)step * 256 + tid] = bt;
            }
            __syncthreads();

            // ---- ct-pass: stream H rows; thread owns cols 2*tid, 2*tid+1 ----
            {
                const __half* hb = g_Hh + (size_t)b * 131072;
                float2 acc = make_float2(0.f, 0.f);
                {
                    const __half* src = hb + tid * 8;
                    unsigned dst = sb_u32 + tid * 16;
#pragma unroll
                    for (int j = 0; j < 4; j++)
                        cp16(dst + j * 4096, src + j * 2048);
                    CP_COMMIT();
                }
                for (int c = 0; c < 16; c++) {
                    if (c < 15) {
                        const __half* src = hb + (c + 1) * 8192 + tid * 8;
                        unsigned dst = sb_u32 + ((c + 1) & 1) * 16384 + tid * 16;
#pragma unroll
                        for (int j = 0; j < 4; j++)
                            cp16(dst + j * 4096, src + j * 2048);
                        CP_COMMIT();
                        CP_WAIT1();
                    } else {
                        CP_WAIT0();
                    }
                    __syncthreads();
                    const __half* base = sbuf + (c & 1) * 8192;
                    const float* bp = &beta[c * 16];
#pragma unroll
                    for (int rr = 0; rr < 16; rr++) {
                        float2 hf = __half22float2(
                            *(const __half2*)(base + rr * 512 + tid * 2));
                        float bv = bp[rr];
                        acc.x += bv * hf.x;
                        acc.y += bv * hf.y;
                    }
                    __syncthreads();
                }
                *(float2*)&g_ct[b * 512 + tid * 2] = acc;
                *(__half2*)&g_qct[b * 512 + tid * 2] = __floats2half2_rn(acc.x, acc.y);
            }
        }
        gsync();

        // ==== P3: gates GEMM via tensor cores + fused LSTM epilogue ====
        {
            const int bg = bid >> 5;
            const int cg = bid & 31;
            const int b_base = bg * 32;
            const int wm = w & 1, wn = w >> 1;
            const int m_off = wm * 16, n_off = wn * 16;
            const int tq = lane >> 2, tr = lane & 3;

            __half* Ab[2] = { sbuf, sbuf + 2304 };
            __half* Bb[2] = { sbuf + 4608, sbuf + 9216 };
            const unsigned A_u32[2] = { sb_u32, sb_u32 + 4608 };
            const unsigned B_u32[2] = { sb_u32 + 9216, sb_u32 + 18432 };

            float acc0[4] = {0.f, 0.f, 0.f, 0.f};
            float acc1[4] = {0.f, 0.f, 0.f, 0.f};

            {
                const int rowA = tid >> 3, segA = tid & 7;
                cp16(A_u32[0] + (rowA * 72 + segA * 8) * 2,
                     &g_qct[(b_base + rowA) * 512 + segA * 8]);
#pragma unroll
                for (int j = 0; j < 2; j++) {
                    int idx = tid + j * 256;
                    int nB = idx >> 3, segB = idx & 7;
                    cp16(B_u32[0] + (nB * 72 + segB * 8) * 2,
                         &g_Wh[(size_t)(cg * 64 + nB) * 1024 + segB * 8]);
                }
                CP_COMMIT();
            }
            for (int ch = 0; ch < 16; ch++) {
                if (ch < 15) {
                    const int nc = ch + 1, buf = nc & 1;
                    const int kbase = (nc & 7) * 64;
                    const int rowA = tid >> 3, segA = tid & 7;
                    const __half* srcA = (nc < 8)
                        ? &g_qct[(b_base + rowA) * 512 + kbase + segA * 8]
                        : &qh_cur[(b_base + rowA) * 1024 + kbase + segA * 8];
                    cp16(A_u32[buf] + (rowA * 72 + segA * 8) * 2, srcA);
#pragma unroll
                    for (int j = 0; j < 2; j++) {
                        int idx = tid + j * 256;
                        int nB = idx >> 3, segB = idx & 7;
                        cp16(B_u32[buf] + (nB * 72 + segB * 8) * 2,
                             &g_Wh[(size_t)(cg * 64 + nB) * 1024 + nc * 64 + segB * 8]);
                    }
                    CP_COMMIT();
                    CP_WAIT1();
                } else {
                    CP_WAIT0();
                }
                __syncthreads();

                const __half* A = Ab[ch & 1];
                const __half* B = Bb[ch & 1];
#pragma unroll
                for (int ks = 0; ks < 4; ks++) {
                    const int kc = ks * 16 + tr * 2;
                    unsigned a0 = *(const unsigned*)&A[(m_off + tq) * 72 + kc];
                    unsigned a1 = *(const unsigned*)&A[(m_off + tq + 8) * 72 + kc];
                    unsigned a2 = *(const unsigned*)&A[(m_off + tq) * 72 + kc + 8];
                    unsigned a3 = *(const unsigned*)&A[(m_off + tq + 8) * 72 + kc + 8];
                    unsigned b0 = *(const unsigned*)&B[(n_off + tq) * 72 + kc];
                    unsigned b1 = *(const unsigned*)&B[(n_off + tq) * 72 + kc + 8];
                    unsigned b2 = *(const unsigned*)&B[(n_off + 8 + tq) * 72 + kc];
                    unsigned b3 = *(const unsigned*)&B[(n_off + 8 + tq) * 72 + kc + 8];
                    mma16816(acc0, a0, a1, a2, a3, b0, b1);
                    mma16816(acc1, a0, a1, a2, a3, b2, b3);
                }
                __syncthreads();
            }

            // epilogue: gather gates via lane-pair shfl, fused LSTM
#pragma unroll
            for (int t = 0; t < 2; t++) {
                const float* a = t ? acc1 : acc0;
                float pg0 = __shfl_sync(0xffffffffu, a[0], lane | 1);
                float po0 = __shfl_sync(0xffffffffu, a[1], lane | 1);
                float pg1 = __shfl_sync(0xffffffffu, a[2], lane | 1);
                float po1 = __shfl_sync(0xffffffffu, a[3], lane | 1);
                if ((lane & 1) == 0) {
                    const int u = cg * 16 + wn * 4 + t * 2 + (tr >> 1);
                    const float4 bi4 = *(const float4*)&g_bias[u * 4];
                    const int row0 = b_base + m_off + tq;
                    const int row1 = row0 + 8;
                    {
                        float iv = a[0] + bi4.x, fv = a[1] + bi4.y;
                        float gv = pg0 + bi4.z,  ov = po0 + bi4.w;
                        float s_new = sigmoid_fast(fv) * g_s[row0 * 512 + u]
                                    + sigmoid_fast(iv) * tanh_fast(gv);
                        float d_new = sigmoid_fast(ov) * tanh_fast(s_new);
                        g_s[row0 * 512 + u] = s_new;
                        qh_nxt[row0 * 1024 + u]       = __float2half_rn(d_new);
                        qh_nxt[row0 * 1024 + 512 + u] = __float2half_rn(s_new);
                        g_dout[row0 * 512 + u] = d_new;
                    }
                    {
                        float iv = a[2] + bi4.x, fv = a[3] + bi4.y;
                        float gv = pg1 + bi4.z,  ov = po1 + bi4.w;
                        float s_new = sigmoid_fast(fv) * g_s[row1 * 512 + u]
                                    + sigmoid_fast(iv) * tanh_fast(gv);
                        float d_new = sigmoid_fast(ov) * tanh_fast(s_new);
                        g_s[row1 * 512 + u] = s_new;
                        qh_nxt[row1 * 1024 + u]       = __float2half_rn(d_new);
                        qh_nxt[row1 * 1024 + 512 + u] = __float2half_rn(s_new);
                        g_dout[row1 * 512 + u] = d_new;
                    }
                }
            }
            __syncthreads();
        }
        gsync();
    }

    // ---------------- epilogue: out head = [d_final ; ct_last] ----------------
    for (int i = gtid; i < 262144; i += nthr) {
        int b = i >> 10, j = i & 1023;
        out[i] = (j < 512) ? g_dout[b * 512 + j] : g_ct[b * 512 + (j - 512)];
    }
}

// ------------------- launch -------------------
extern "C" void kernel_launch(void* const* d_in, const int* in_sizes, int n_in,
                              void* d_out, int out_size) {
    (void)in_sizes; (void)n_in; (void)out_size;
    const float* H    = (const float*)d_in[0];
    const float* d0   = (const float*)d_in[1];
    const float* s0   = (const float*)d_in[2];
    const float* W_d  = (const float*)d_in[3];
    const float* U_d  = (const float*)d_in[4];
    const float* v_d  = (const float*)d_in[5];
    const float* W_ih = (const float*)d_in[6];
    const float* W_hh = (const float*)d_in[7];
    const float* b_ih = (const float*)d_in[8];
    const float* b_hh = (const float*)d_in[9];
    float* out = (float*)d_out;

    k_decoder<<<GBLK, 256>>>(H, d0, s0, W_d, U_d, v_d, W_ih, W_hh, b_ih, b_hh, out);
}